// round 1
// baseline (speedup 1.0000x reference)
#include <cuda_runtime.h>
#include <math.h>

// Problem constants
constexpr int B   = 16;
constexpr int H   = 8;
constexpr int N1  = 256;
constexpr int N2  = 576;
constexpr int HD  = 64;
constexpr int DIM = 512;
constexpr int BH  = B * H;       // 128
constexpr int ITERS = 100;

// Static scratch (no runtime allocation allowed)
__device__ float g_tq[B * N1 * DIM];      // F_t @ Wq^T + bq   [B*N1, 512]
__device__ float g_tk[B * N2 * DIM];
__device__ float g_tv[B * N2 * DIM];
__device__ float g_q[BH * N1 * HD];       // [B,H,N1,64] normalized
__device__ float g_k[BH * N2 * HD];
__device__ float g_v[BH * N2 * HD];
__device__ float g_sim[(size_t)BH * N1 * N2];
__device__ float g_A[(size_t)BH * N1 * N2];   // exp((sim-1)/eps)
__device__ float g_alpha[BH * N1];
__device__ float g_beta[BH * N2];
__device__ float g_ctx[B * N1 * DIM];     // attention output, [B*N1, 512]

// ---------------------------------------------------------------------------
// Generic fp32 GEMM: out[M,N] = X[M,K] @ W[N,K]^T + bias[N]
// 64x64 tile, BK=16, 256 threads, 4x4 per thread. M,N,K all multiples of 64/16.
// ---------------------------------------------------------------------------
__global__ __launch_bounds__(256) void gemm_xwT_kernel(
    const float* __restrict__ X, const float* __restrict__ W,
    const float* __restrict__ bias, float* __restrict__ out,
    int M, int N, int K)
{
    __shared__ float Xs[16][68];
    __shared__ float Ws[16][68];
    const int tid = threadIdx.x;
    const int tx = tid & 15, ty = tid >> 4;
    const int bm = blockIdx.y * 64, bn = blockIdx.x * 64;
    const int lr = tid >> 2;            // 0..63
    const int lc = (tid & 3) << 2;      // 0,4,8,12

    float acc[4][4];
#pragma unroll
    for (int i = 0; i < 4; i++)
#pragma unroll
        for (int j = 0; j < 4; j++) acc[i][j] = 0.f;

    for (int k0 = 0; k0 < K; k0 += 16) {
        float4 xv = *(const float4*)(X + (size_t)(bm + lr) * K + k0 + lc);
        float4 wv = *(const float4*)(W + (size_t)(bn + lr) * K + k0 + lc);
        Xs[lc + 0][lr] = xv.x; Xs[lc + 1][lr] = xv.y; Xs[lc + 2][lr] = xv.z; Xs[lc + 3][lr] = xv.w;
        Ws[lc + 0][lr] = wv.x; Ws[lc + 1][lr] = wv.y; Ws[lc + 2][lr] = wv.z; Ws[lc + 3][lr] = wv.w;
        __syncthreads();
#pragma unroll
        for (int kk = 0; kk < 16; kk++) {
            float4 a = *(const float4*)&Xs[kk][ty << 2];
            float4 b = *(const float4*)&Ws[kk][tx << 2];
            float av_[4] = {a.x, a.y, a.z, a.w};
            float bv_[4] = {b.x, b.y, b.z, b.w};
#pragma unroll
            for (int i = 0; i < 4; i++)
#pragma unroll
                for (int j = 0; j < 4; j++) acc[i][j] += av_[i] * bv_[j];
        }
        __syncthreads();
    }
#pragma unroll
    for (int i = 0; i < 4; i++) {
        int r = bm + (ty << 2) + i;
#pragma unroll
        for (int j = 0; j < 4; j++) {
            int c = bn + (tx << 2) + j;
            out[(size_t)r * N + c] = acc[i][j] + bias[c];
        }
    }
}

// ---------------------------------------------------------------------------
// Transpose [B, Nn, H*64] -> [B, H, Nn, 64], with optional L2-normalization
// (clamped: x / max(||x||, 1e-12)). One warp per (b,n,h) row of 64.
// ---------------------------------------------------------------------------
__global__ void qk_transnorm_kernel(const float* __restrict__ src,
                                    float* __restrict__ dst, int Nn, int do_norm)
{
    int gw = (int)((blockIdx.x * blockDim.x + threadIdx.x) >> 5);
    int lane = threadIdx.x & 31;
    int total = B * Nn * H;
    if (gw >= total) return;
    int h = gw % H;
    int n = (gw / H) % Nn;
    int b = gw / (H * Nn);
    const float* sp = src + (size_t)(b * Nn + n) * DIM + h * HD;
    float2 x = *(const float2*)(sp + lane * 2);
    float s = 1.f;
    if (do_norm) {
        float ss = x.x * x.x + x.y * x.y;
#pragma unroll
        for (int o = 16; o > 0; o >>= 1) ss += __shfl_xor_sync(0xffffffffu, ss, o);
        s = 1.0f / fmaxf(sqrtf(ss), 1e-12f);
    }
    float* dp = dst + (size_t)((b * H + h) * Nn + n) * HD;
    *(float2*)(dp + lane * 2) = make_float2(x.x * s, x.y * s);
}

// ---------------------------------------------------------------------------
// sim[bh,i,j] = q[bh,i,:] . k[bh,j,:]   (beta_t = 1)
// A = exp((sim - 1) / eps),  eps = 0.05  ->  exp((sim-1)*20)
// ---------------------------------------------------------------------------
__global__ __launch_bounds__(256) void sim_kernel(
    const float* __restrict__ q, const float* __restrict__ k,
    float* __restrict__ simo, float* __restrict__ Ao)
{
    __shared__ float Qs[64][68];
    __shared__ float Ks[64][68];
    int bh = blockIdx.z;
    int i0 = blockIdx.y * 64, j0 = blockIdx.x * 64;
    const float* qp = q + (size_t)bh * N1 * HD;
    const float* kp = k + (size_t)bh * N2 * HD;
    int tid = threadIdx.x;
    int tx = tid & 15, ty = tid >> 4;
    int lr = tid >> 2;
#pragma unroll
    for (int it = 0; it < 4; it++) {
        int lc = (((tid & 3) + (it << 2)) << 2);
        float4 qv = *(const float4*)(qp + (size_t)(i0 + lr) * HD + lc);
        Qs[lc + 0][lr] = qv.x; Qs[lc + 1][lr] = qv.y; Qs[lc + 2][lr] = qv.z; Qs[lc + 3][lr] = qv.w;
        float4 kv = *(const float4*)(kp + (size_t)(j0 + lr) * HD + lc);
        Ks[lc + 0][lr] = kv.x; Ks[lc + 1][lr] = kv.y; Ks[lc + 2][lr] = kv.z; Ks[lc + 3][lr] = kv.w;
    }
    __syncthreads();
    float acc[4][4] = {};
#pragma unroll 8
    for (int kk = 0; kk < 64; kk++) {
        float4 a = *(const float4*)&Qs[kk][ty << 2];
        float4 b = *(const float4*)&Ks[kk][tx << 2];
        float av_[4] = {a.x, a.y, a.z, a.w};
        float bv_[4] = {b.x, b.y, b.z, b.w};
#pragma unroll
        for (int i = 0; i < 4; i++)
#pragma unroll
            for (int j = 0; j < 4; j++) acc[i][j] += av_[i] * bv_[j];
    }
    size_t base = (size_t)bh * N1 * N2;
#pragma unroll
    for (int i = 0; i < 4; i++)
#pragma unroll
        for (int j = 0; j < 4; j++) {
            float s = acc[i][j];
            size_t idx = base + (size_t)(i0 + (ty << 2) + i) * N2 + (j0 + (tx << 2) + j);
            simo[idx] = s;
            Ao[idx] = expf((s - 1.0f) * 20.0f);
        }
}

// ---------------------------------------------------------------------------
// Sinkhorn in scaled domain. One CTA per bh slice, 512 threads (16 warps).
// alpha_new = mu / (A beta),  beta_new = nu / (A^T alpha), both with OLD values
// -> single pass over A per iteration computing both sums.
// ---------------------------------------------------------------------------
__global__ __launch_bounds__(512) void sinkhorn_kernel(
    const float* __restrict__ A_all, float* __restrict__ alpha_out,
    float* __restrict__ beta_out)
{
    __shared__ float s_alpha[N1];
    __shared__ float s_beta[N2];
    __shared__ float s_r[N1];
    __shared__ float s_cpart[16][N2];

    int bh = blockIdx.x;
    const float* A = A_all + (size_t)bh * N1 * N2;
    int tid = threadIdx.x, lane = tid & 31, w = tid >> 5;

    for (int i = tid; i < N1; i += 512) s_alpha[i] = 1.f;
    for (int j = tid; j < N2; j += 512) s_beta[j] = 1.f;
    __syncthreads();

    const float MU = 1.0f / 256.0f + 1e-8f;
    const float NU = 1.0f / 576.0f + 1e-8f;

#pragma unroll 1
    for (int it = 0; it < ITERS; it++) {
        float pb[18], pc[18];
#pragma unroll
        for (int t = 0; t < 18; t++) { pb[t] = s_beta[lane + 32 * t]; pc[t] = 0.f; }

#pragma unroll 1
        for (int rr = 0; rr < 16; rr++) {
            int i = w * 16 + rr;                 // this warp owns 16 full rows
            float ai = s_alpha[i];
            float accr = 0.f;
            const float* row = A + (size_t)i * N2 + lane;
#pragma unroll
            for (int t = 0; t < 18; t++) {
                float a = row[32 * t];
                accr += a * pb[t];               // row sum  (A beta)
                pc[t] += a * ai;                 // col partial (A^T alpha)
            }
#pragma unroll
            for (int o = 16; o > 0; o >>= 1) accr += __shfl_xor_sync(0xffffffffu, accr, o);
            if (lane == 0) s_r[i] = accr;
        }
#pragma unroll
        for (int t = 0; t < 18; t++) s_cpart[w][lane + 32 * t] = pc[t];
        __syncthreads();

        if (tid < N1) s_alpha[tid] = MU / s_r[tid];
        for (int j = tid; j < N2; j += 512) {
            float sc = 0.f;
#pragma unroll
            for (int ww = 0; ww < 16; ww++) sc += s_cpart[ww][j];
            s_beta[j] = NU / sc;
        }
        __syncthreads();
    }

    for (int i = tid; i < N1; i += 512) alpha_out[bh * N1 + i] = s_alpha[i];
    for (int j = tid; j < N2; j += 512) beta_out[bh * N2 + j] = s_beta[j];
}

// ---------------------------------------------------------------------------
// ctx[b, n, h*64+c] = sum_m (N1*N2 * sim * A * alpha_n * beta_m) * v[bh, m, c]
// ---------------------------------------------------------------------------
__global__ __launch_bounds__(256) void av_kernel(
    const float* __restrict__ sim_all, const float* __restrict__ A_all,
    const float* __restrict__ v_all, const float* __restrict__ alpha,
    const float* __restrict__ beta, float* __restrict__ ctx)
{
    __shared__ float Ss[64][68];   // [m][n]
    __shared__ float Vs[64][68];   // [m][c]
    __shared__ float sa[64];
    __shared__ float sb[64];
    int bh = blockIdx.y;
    int n0 = blockIdx.x * 64;
    const float* simp = sim_all + (size_t)bh * N1 * N2;
    const float* Ap   = A_all   + (size_t)bh * N1 * N2;
    const float* vp   = v_all   + (size_t)bh * N2 * HD;
    int tid = threadIdx.x, tx = tid & 15, ty = tid >> 4;
    int lr = tid >> 2;

    if (tid < 64) sa[tid] = alpha[bh * N1 + n0 + tid] * 147456.0f;  // fold N1*N2

    float acc[4][4] = {};
    for (int m0 = 0; m0 < N2; m0 += 64) {
        if (tid < 64) sb[tid] = beta[bh * N2 + m0 + tid];
        __syncthreads();          // guards sa/sb visible + previous compute done
#pragma unroll
        for (int it = 0; it < 4; it++) {
            int lc = (((tid & 3) + (it << 2)) << 2);
            size_t idx = (size_t)(n0 + lr) * N2 + m0 + lc;
            float4 sv = *(const float4*)(simp + idx);
            float4 avv = *(const float4*)(Ap + idx);
            float an = sa[lr];
            Ss[lc + 0][lr] = sv.x * avv.x * an * sb[lc + 0];
            Ss[lc + 1][lr] = sv.y * avv.y * an * sb[lc + 1];
            Ss[lc + 2][lr] = sv.z * avv.z * an * sb[lc + 2];
            Ss[lc + 3][lr] = sv.w * avv.w * an * sb[lc + 3];
            float4 vv = *(const float4*)(vp + (size_t)(m0 + lr) * HD + lc);
            *(float4*)&Vs[lr][lc] = vv;
        }
        __syncthreads();
#pragma unroll 8
        for (int kk = 0; kk < 64; kk++) {
            float4 a = *(const float4*)&Ss[kk][ty << 2];
            float4 b = *(const float4*)&Vs[kk][tx << 2];
            float av_[4] = {a.x, a.y, a.z, a.w};
            float bv_[4] = {b.x, b.y, b.z, b.w};
#pragma unroll
            for (int i = 0; i < 4; i++)
#pragma unroll
                for (int j = 0; j < 4; j++) acc[i][j] += av_[i] * bv_[j];
        }
    }
    int b = bh >> 3, h = bh & 7;
#pragma unroll
    for (int i = 0; i < 4; i++)
#pragma unroll
        for (int j = 0; j < 4; j++) {
            ctx[(size_t)(b * N1 + n0 + (ty << 2) + i) * DIM + h * HD + (tx << 2) + j] = acc[i][j];
        }
}

// ---------------------------------------------------------------------------
// In-place row L2 normalization (plain divide, no clamp): rows of 512 floats
// ---------------------------------------------------------------------------
__global__ __launch_bounds__(128) void norm_rows_kernel(float* __restrict__ out)
{
    __shared__ float red[4];
    int row = blockIdx.x;
    float4* p = (float4*)(out + (size_t)row * DIM);
    int tid = threadIdx.x;
    float4 v = p[tid];
    float ss = v.x * v.x + v.y * v.y + v.z * v.z + v.w * v.w;
#pragma unroll
    for (int o = 16; o > 0; o >>= 1) ss += __shfl_xor_sync(0xffffffffu, ss, o);
    if ((tid & 31) == 0) red[tid >> 5] = ss;
    __syncthreads();
    float tot = red[0] + red[1] + red[2] + red[3];
    float inv = 1.0f / sqrtf(tot);
    v.x *= inv; v.y *= inv; v.z *= inv; v.w *= inv;
    p[tid] = v;
}

// ---------------------------------------------------------------------------
extern "C" void kernel_launch(void* const* d_in, const int* in_sizes, int n_in,
                              void* d_out, int out_size)
{
    (void)in_sizes; (void)n_in; (void)out_size;
    const float* F_t = (const float*)d_in[0];
    const float* F_s = (const float*)d_in[1];
    const float* Wq  = (const float*)d_in[2];
    const float* bq  = (const float*)d_in[3];
    const float* Wk  = (const float*)d_in[4];
    const float* bk  = (const float*)d_in[5];
    const float* Wv  = (const float*)d_in[6];
    const float* bv  = (const float*)d_in[7];
    const float* Wp  = (const float*)d_in[8];
    const float* bp  = (const float*)d_in[9];
    float* out = (float*)d_out;

    float *tq, *tk, *tv, *q, *k, *v, *simb, *Ab, *alpha, *beta, *ctx;
    cudaGetSymbolAddress((void**)&tq, g_tq);
    cudaGetSymbolAddress((void**)&tk, g_tk);
    cudaGetSymbolAddress((void**)&tv, g_tv);
    cudaGetSymbolAddress((void**)&q, g_q);
    cudaGetSymbolAddress((void**)&k, g_k);
    cudaGetSymbolAddress((void**)&v, g_v);
    cudaGetSymbolAddress((void**)&simb, g_sim);
    cudaGetSymbolAddress((void**)&Ab, g_A);
    cudaGetSymbolAddress((void**)&alpha, g_alpha);
    cudaGetSymbolAddress((void**)&beta, g_beta);
    cudaGetSymbolAddress((void**)&ctx, g_ctx);

    // 1) QKV projections (conv1d k=1 == pointwise linear)
    gemm_xwT_kernel<<<dim3(DIM / 64, B * N1 / 64), 256>>>(F_t, Wq, bq, tq, B * N1, DIM, DIM);
    gemm_xwT_kernel<<<dim3(DIM / 64, B * N2 / 64), 256>>>(F_s, Wk, bk, tk, B * N2, DIM, DIM);
    gemm_xwT_kernel<<<dim3(DIM / 64, B * N2 / 64), 256>>>(F_s, Wv, bv, tv, B * N2, DIM, DIM);

    // 2) transpose to [B,H,Nx,64] (+ l2norm for q,k)
    {
        int warps_q = B * N1 * H;
        int warps_k = B * N2 * H;
        qk_transnorm_kernel<<<(warps_q * 32 + 255) / 256, 256>>>(tq, q, N1, 1);
        qk_transnorm_kernel<<<(warps_k * 32 + 255) / 256, 256>>>(tk, k, N2, 1);
        qk_transnorm_kernel<<<(warps_k * 32 + 255) / 256, 256>>>(tv, v, N2, 0);
    }

    // 3) sim + Gibbs kernel A = exp((sim-1)/eps)
    sim_kernel<<<dim3(N2 / 64, N1 / 64, BH), 256>>>(q, k, simb, Ab);

    // 4) 100 Sinkhorn iterations, one CTA per (b,h) slice
    sinkhorn_kernel<<<BH, 512>>>(Ab, alpha, beta);

    // 5) score @ v -> ctx [B*N1, 512]
    av_kernel<<<dim3(N1 / 64, BH), 256>>>(simb, Ab, v, alpha, beta, ctx);

    // 6) projection + 7) row normalize (in place in d_out)
    gemm_xwT_kernel<<<dim3(DIM / 64, B * N1 / 64), 256>>>(ctx, Wp, bp, out, B * N1, DIM, DIM);
    norm_rows_kernel<<<B * N1, 128>>>(out);
}

// round 3
// speedup vs baseline: 1.0962x; 1.0962x over previous
#include <cuda_runtime.h>
#include <cuda_bf16.h>
#include <math.h>

// Problem constants
constexpr int B   = 16;
constexpr int H   = 8;
constexpr int N1  = 256;
constexpr int N2  = 576;
constexpr int HD  = 64;
constexpr int DIM = 512;
constexpr int BH  = B * H;       // 128
constexpr int ITERS = 100;

typedef unsigned long long u64;
typedef unsigned int u32;

// ---- packed f32x2 helpers (sm_103a FFMA2; ptxas never auto-fuses) ----
__device__ __forceinline__ u64 ffma2(u64 a, u64 b, u64 c) {
    u64 d; asm("fma.rn.f32x2 %0,%1,%2,%3;" : "=l"(d) : "l"(a), "l"(b), "l"(c)); return d;
}
__device__ __forceinline__ u64 pack2(float x, float y) {
    u64 d; asm("mov.b64 %0,{%1,%2};" : "=l"(d) : "f"(x), "f"(y)); return d;
}
__device__ __forceinline__ float2 unpack2(u64 d) {
    float2 r; asm("mov.b64 {%0,%1},%2;" : "=f"(r.x), "=f"(r.y) : "l"(d)); return r;
}

// Static scratch (no runtime allocation allowed)
__device__ float g_tq[B * N1 * DIM];
__device__ float g_tk[B * N2 * DIM];
__device__ float g_tv[B * N2 * DIM];
__device__ float g_q[BH * N1 * HD];
__device__ float g_k[BH * N2 * HD];
__device__ float g_v[BH * N2 * HD];
__device__ float g_sim[(size_t)BH * N1 * N2];                  // fp32 sim (exact)
__device__ __nv_bfloat16 g_A16[(size_t)BH * N1 * N2];          // bf16 Gibbs kernel for Sinkhorn
__device__ float g_alpha[BH * N1];
__device__ float g_beta[BH * N2];
__device__ float g_ctx[B * N1 * DIM];

// ---------------------------------------------------------------------------
// fp32 GEMM, 128x128 tile, 256 threads, 8x8/thread (2x2 quadrants of 4x4),
// FFMA2 inner product:  out[M,N] = X[M,K] @ W[N,K]^T + bias[N]
// M,N,K multiples of 128/16.
// ---------------------------------------------------------------------------
__global__ __launch_bounds__(256) void gemm128_kernel(
    const float* __restrict__ X, const float* __restrict__ W,
    const float* __restrict__ bias, float* __restrict__ out,
    int M, int N, int K)
{
    __shared__ __align__(16) float Xs[16][132];
    __shared__ __align__(16) float Ws[16][132];
    const int tid = threadIdx.x;
    const int tx = tid & 15, ty = tid >> 4;
    const int bm = blockIdx.y * 128, bn = blockIdx.x * 128;
    const int lr = tid >> 1;            // 0..127
    const int lc = (tid & 1) * 8;       // 0 or 8

    u64 acc[2][2][4][2];
#pragma unroll
    for (int iq = 0; iq < 2; iq++)
#pragma unroll
        for (int jq = 0; jq < 2; jq++)
#pragma unroll
            for (int i = 0; i < 4; i++) { acc[iq][jq][i][0] = 0ull; acc[iq][jq][i][1] = 0ull; }

    const float* Xp = X + (size_t)(bm + lr) * K + lc;
    const float* Wp = W + (size_t)(bn + lr) * K + lc;

    for (int k0 = 0; k0 < K; k0 += 16) {
        float4 x0 = *(const float4*)(Xp + k0);
        float4 x1 = *(const float4*)(Xp + k0 + 4);
        float4 w0 = *(const float4*)(Wp + k0);
        float4 w1 = *(const float4*)(Wp + k0 + 4);
        Xs[lc + 0][lr] = x0.x; Xs[lc + 1][lr] = x0.y; Xs[lc + 2][lr] = x0.z; Xs[lc + 3][lr] = x0.w;
        Xs[lc + 4][lr] = x1.x; Xs[lc + 5][lr] = x1.y; Xs[lc + 6][lr] = x1.z; Xs[lc + 7][lr] = x1.w;
        Ws[lc + 0][lr] = w0.x; Ws[lc + 1][lr] = w0.y; Ws[lc + 2][lr] = w0.z; Ws[lc + 3][lr] = w0.w;
        Ws[lc + 4][lr] = w1.x; Ws[lc + 5][lr] = w1.y; Ws[lc + 6][lr] = w1.z; Ws[lc + 7][lr] = w1.w;
        __syncthreads();
#pragma unroll
        for (int kk = 0; kk < 16; kk++) {
            float4 a0 = *(const float4*)&Xs[kk][ty * 4];
            float4 a1 = *(const float4*)&Xs[kk][64 + ty * 4];
            float4 b0 = *(const float4*)&Ws[kk][tx * 4];
            float4 b1 = *(const float4*)&Ws[kk][64 + tx * 4];
            u64 bp[2][2] = {{pack2(b0.x, b0.y), pack2(b0.z, b0.w)},
                            {pack2(b1.x, b1.y), pack2(b1.z, b1.w)}};
            float av[2][4] = {{a0.x, a0.y, a0.z, a0.w}, {a1.x, a1.y, a1.z, a1.w}};
#pragma unroll
            for (int iq = 0; iq < 2; iq++)
#pragma unroll
                for (int i = 0; i < 4; i++) {
                    u64 ad = pack2(av[iq][i], av[iq][i]);
#pragma unroll
                    for (int jq = 0; jq < 2; jq++) {
                        acc[iq][jq][i][0] = ffma2(ad, bp[jq][0], acc[iq][jq][i][0]);
                        acc[iq][jq][i][1] = ffma2(ad, bp[jq][1], acc[iq][jq][i][1]);
                    }
                }
        }
        __syncthreads();
    }
#pragma unroll
    for (int iq = 0; iq < 2; iq++)
#pragma unroll
        for (int i = 0; i < 4; i++) {
            int r = bm + iq * 64 + ty * 4 + i;
#pragma unroll
            for (int jq = 0; jq < 2; jq++) {
                int c = bn + jq * 64 + tx * 4;
                float2 p0 = unpack2(acc[iq][jq][i][0]);
                float2 p1 = unpack2(acc[iq][jq][i][1]);
                float4 o = make_float4(p0.x + bias[c], p0.y + bias[c + 1],
                                       p1.x + bias[c + 2], p1.y + bias[c + 3]);
                *(float4*)(out + (size_t)r * N + c) = o;
            }
        }
}

// ---------------------------------------------------------------------------
// Transpose [B, Nn, H*64] -> [B, H, Nn, 64], optional L2 norm (clamped)
// ---------------------------------------------------------------------------
__global__ void qk_transnorm_kernel(const float* __restrict__ src,
                                    float* __restrict__ dst, int Nn, int do_norm)
{
    int gw = (int)((blockIdx.x * blockDim.x + threadIdx.x) >> 5);
    int lane = threadIdx.x & 31;
    int total = B * Nn * H;
    if (gw >= total) return;
    int h = gw % H;
    int n = (gw / H) % Nn;
    int b = gw / (H * Nn);
    const float* sp = src + (size_t)(b * Nn + n) * DIM + h * HD;
    float2 x = *(const float2*)(sp + lane * 2);
    float s = 1.f;
    if (do_norm) {
        float ss = x.x * x.x + x.y * x.y;
#pragma unroll
        for (int o = 16; o > 0; o >>= 1) ss += __shfl_xor_sync(0xffffffffu, ss, o);
        s = 1.0f / fmaxf(sqrtf(ss), 1e-12f);
    }
    float* dp = dst + (size_t)((b * H + h) * Nn + n) * HD;
    *(float2*)(dp + lane * 2) = make_float2(x.x * s, x.y * s);
}

// ---------------------------------------------------------------------------
// sim = q.k (beta_t=1), store fp32 sim and bf16 A = exp((sim-1)*20)
// ---------------------------------------------------------------------------
__global__ __launch_bounds__(256) void sim_kernel(
    const float* __restrict__ q, const float* __restrict__ k,
    float* __restrict__ simo, __nv_bfloat16* __restrict__ Ao)
{
    __shared__ __align__(16) float Qs[64][68];
    __shared__ __align__(16) float Ks[64][68];
    int bh = blockIdx.z;
    int i0 = blockIdx.y * 64, j0 = blockIdx.x * 64;
    const float* qp = q + (size_t)bh * N1 * HD;
    const float* kp = k + (size_t)bh * N2 * HD;
    int tid = threadIdx.x;
    int tx = tid & 15, ty = tid >> 4;
    int lr = tid >> 2;
#pragma unroll
    for (int it = 0; it < 4; it++) {
        int lc = (((tid & 3) + (it << 2)) << 2);
        float4 qv = *(const float4*)(qp + (size_t)(i0 + lr) * HD + lc);
        Qs[lc + 0][lr] = qv.x; Qs[lc + 1][lr] = qv.y; Qs[lc + 2][lr] = qv.z; Qs[lc + 3][lr] = qv.w;
        float4 kv = *(const float4*)(kp + (size_t)(j0 + lr) * HD + lc);
        Ks[lc + 0][lr] = kv.x; Ks[lc + 1][lr] = kv.y; Ks[lc + 2][lr] = kv.z; Ks[lc + 3][lr] = kv.w;
    }
    __syncthreads();
    u64 acc2[4][2];
#pragma unroll
    for (int i = 0; i < 4; i++) { acc2[i][0] = 0ull; acc2[i][1] = 0ull; }
#pragma unroll 8
    for (int kk = 0; kk < 64; kk++) {
        float4 a = *(const float4*)&Qs[kk][ty << 2];
        float4 b = *(const float4*)&Ks[kk][tx << 2];
        u64 b01 = pack2(b.x, b.y), b23 = pack2(b.z, b.w);
        float av[4] = {a.x, a.y, a.z, a.w};
#pragma unroll
        for (int i = 0; i < 4; i++) {
            u64 ad = pack2(av[i], av[i]);
            acc2[i][0] = ffma2(ad, b01, acc2[i][0]);
            acc2[i][1] = ffma2(ad, b23, acc2[i][1]);
        }
    }
    size_t base = (size_t)bh * N1 * N2;
#pragma unroll
    for (int i = 0; i < 4; i++) {
        size_t idx = base + (size_t)(i0 + (ty << 2) + i) * N2 + (j0 + (tx << 2));
        float2 p0 = unpack2(acc2[i][0]);
        float2 p1 = unpack2(acc2[i][1]);
        *(float4*)(simo + idx) = make_float4(p0.x, p0.y, p1.x, p1.y);
        __nv_bfloat162* A2 = (__nv_bfloat162*)(Ao + idx);
        A2[0] = __floats2bfloat162_rn(__expf((p0.x - 1.0f) * 20.0f),
                                      __expf((p0.y - 1.0f) * 20.0f));
        A2[1] = __floats2bfloat162_rn(__expf((p1.x - 1.0f) * 20.0f),
                                      __expf((p1.y - 1.0f) * 20.0f));
    }
}

// ---------------------------------------------------------------------------
// Sinkhorn (scaled domain), bf16 A, one CTA per bh slice, 512 threads.
// Single pass per iteration computes A.beta (rows) and A^T.alpha (cols)
// with the OLD (alpha,beta) -- algebraically identical to the reference.
// Early-exit when max relative change < 1e-6 (below fp32 significance).
// ---------------------------------------------------------------------------
__global__ __launch_bounds__(512) void sinkhorn_kernel(
    const __nv_bfloat16* __restrict__ A16, float* __restrict__ alpha_out,
    float* __restrict__ beta_out)
{
    __shared__ __align__(16) float s_alpha[N1];
    __shared__ __align__(16) float s_beta[N2];
    __shared__ __align__(16) float s_r[N1];
    __shared__ __align__(16) float s_cpart[16][N2];
    __shared__ float s_wmax[16];

    int bh = blockIdx.x;
    const u32* A = (const u32*)(A16 + (size_t)bh * N1 * N2);  // 288 u32 per row
    int tid = threadIdx.x, lane = tid & 31, w = tid >> 5;

    for (int i = tid; i < N1; i += 512) s_alpha[i] = 1.f;
    for (int j = tid; j < N2; j += 512) s_beta[j] = 1.f;
    __syncthreads();

    const float MU = 1.0f / 256.0f + 1e-8f;
    const float NU = 1.0f / 576.0f + 1e-8f;

#pragma unroll 1
    for (int it = 0; it < ITERS; it++) {
        u64 pb[9], pc[9];
        const u64* sb2 = (const u64*)s_beta;
#pragma unroll
        for (int t = 0; t < 9; t++) { pb[t] = sb2[lane + 32 * t]; pc[t] = 0ull; }

#pragma unroll 1
        for (int rr = 0; rr < 16; rr++) {
            int i = w * 16 + rr;
            float ai = s_alpha[i];
            u64 ad = pack2(ai, ai);
            u64 accr2 = 0ull;
            const u32* row = A + i * 288 + lane;
#pragma unroll
            for (int t = 0; t < 9; t++) {
                u32 x = row[32 * t];
                u64 a2 = ((u64)(x & 0xffff0000u) << 32) | (u64)(x << 16);  // 2 bf16 -> f32x2
                accr2 = ffma2(a2, pb[t], accr2);   // row sum   (A beta)
                pc[t] = ffma2(a2, ad, pc[t]);      // col parts (A^T alpha)
            }
            float2 ar = unpack2(accr2);
            float accr = ar.x + ar.y;
#pragma unroll
            for (int o = 16; o > 0; o >>= 1) accr += __shfl_xor_sync(0xffffffffu, accr, o);
            if (lane == 0) s_r[i] = accr;
        }
        u64* cp2 = (u64*)&s_cpart[w][0];
#pragma unroll
        for (int t = 0; t < 9; t++) cp2[lane + 32 * t] = pc[t];
        __syncthreads();

        float mx = 0.f;
        if (tid < N1) {
            float na = MU / s_r[tid];
            mx = fabsf(na - s_alpha[tid]) / na;
            s_alpha[tid] = na;
        }
        for (int j = tid; j < N2; j += 512) {
            float sc = 0.f;
#pragma unroll
            for (int ww = 0; ww < 16; ww++) sc += s_cpart[ww][j];
            float nb = NU / sc;
            mx = fmaxf(mx, fabsf(nb - s_beta[j]) / nb);
            s_beta[j] = nb;
        }
#pragma unroll
        for (int o = 16; o > 0; o >>= 1) mx = fmaxf(mx, __shfl_xor_sync(0xffffffffu, mx, o));
        if (lane == 0) s_wmax[w] = mx;
        __syncthreads();
        float m = 0.f;
#pragma unroll
        for (int ww = 0; ww < 16; ww++) m = fmaxf(m, s_wmax[ww]);
        if (m < 1e-6f) break;   // converged to fp32 significance; rest are no-ops
    }

    for (int i = tid; i < N1; i += 512) alpha_out[bh * N1 + i] = s_alpha[i];
    for (int j = tid; j < N2; j += 512) beta_out[bh * N2 + j] = s_beta[j];
}

// ---------------------------------------------------------------------------
// ctx = (N1*N2 * sim * exp((sim-1)*20) * alpha_n * beta_m) @ v   (fp32 A here)
// ---------------------------------------------------------------------------
__global__ __launch_bounds__(256) void av_kernel(
    const float* __restrict__ sim_all, const float* __restrict__ v_all,
    const float* __restrict__ alpha, const float* __restrict__ beta,
    float* __restrict__ ctx)
{
    __shared__ __align__(16) float Ss[64][68];   // [m][n]
    __shared__ __align__(16) float Vs[64][68];   // [m][c]
    __shared__ float sa[64];
    __shared__ float sb[64];
    int bh = blockIdx.y;
    int n0 = blockIdx.x * 64;
    const float* simp = sim_all + (size_t)bh * N1 * N2;
    const float* vp   = v_all   + (size_t)bh * N2 * HD;
    int tid = threadIdx.x, tx = tid & 15, ty = tid >> 4;
    int lr = tid >> 2;

    if (tid < 64) sa[tid] = alpha[bh * N1 + n0 + tid] * 147456.0f;  // fold N1*N2

    u64 acc2[4][2];
#pragma unroll
    for (int i = 0; i < 4; i++) { acc2[i][0] = 0ull; acc2[i][1] = 0ull; }

    for (int m0 = 0; m0 < N2; m0 += 64) {
        if (tid < 64) sb[tid] = beta[bh * N2 + m0 + tid];
        __syncthreads();
#pragma unroll
        for (int it = 0; it < 4; it++) {
            int lc = (((tid & 3) + (it << 2)) << 2);
            size_t idx = (size_t)(n0 + lr) * N2 + m0 + lc;
            float4 sv = *(const float4*)(simp + idx);
            float an = sa[lr];
            Ss[lc + 0][lr] = sv.x * __expf((sv.x - 1.0f) * 20.0f) * an * sb[lc + 0];
            Ss[lc + 1][lr] = sv.y * __expf((sv.y - 1.0f) * 20.0f) * an * sb[lc + 1];
            Ss[lc + 2][lr] = sv.z * __expf((sv.z - 1.0f) * 20.0f) * an * sb[lc + 2];
            Ss[lc + 3][lr] = sv.w * __expf((sv.w - 1.0f) * 20.0f) * an * sb[lc + 3];
            float4 vv = *(const float4*)(vp + (size_t)(m0 + lr) * HD + lc);
            *(float4*)&Vs[lr][lc] = vv;
        }
        __syncthreads();
#pragma unroll 8
        for (int kk = 0; kk < 64; kk++) {
            float4 a = *(const float4*)&Ss[kk][ty << 2];
            float4 b = *(const float4*)&Vs[kk][tx << 2];
            u64 b01 = pack2(b.x, b.y), b23 = pack2(b.z, b.w);
            float av[4] = {a.x, a.y, a.z, a.w};
#pragma unroll
            for (int i = 0; i < 4; i++) {
                u64 ad = pack2(av[i], av[i]);
                acc2[i][0] = ffma2(ad, b01, acc2[i][0]);
                acc2[i][1] = ffma2(ad, b23, acc2[i][1]);
            }
        }
    }
    int b = bh >> 3, h = bh & 7;
#pragma unroll
    for (int i = 0; i < 4; i++) {
        float2 p0 = unpack2(acc2[i][0]);
        float2 p1 = unpack2(acc2[i][1]);
        float* dst = ctx + (size_t)(b * N1 + n0 + (ty << 2) + i) * DIM + h * HD + (tx << 2);
        *(float4*)dst = make_float4(p0.x, p0.y, p1.x, p1.y);
    }
}

// ---------------------------------------------------------------------------
// In-place row L2 normalization (plain divide): rows of 512 floats
// ---------------------------------------------------------------------------
__global__ __launch_bounds__(128) void norm_rows_kernel(float* __restrict__ out)
{
    __shared__ float red[4];
    int row = blockIdx.x;
    float4* p = (float4*)(out + (size_t)row * DIM);
    int tid = threadIdx.x;
    float4 v = p[tid];
    float ss = v.x * v.x + v.y * v.y + v.z * v.z + v.w * v.w;
#pragma unroll
    for (int o = 16; o > 0; o >>= 1) ss += __shfl_xor_sync(0xffffffffu, ss, o);
    if ((tid & 31) == 0) red[tid >> 5] = ss;
    __syncthreads();
    float tot = red[0] + red[1] + red[2] + red[3];
    float inv = 1.0f / sqrtf(tot);
    v.x *= inv; v.y *= inv; v.z *= inv; v.w *= inv;
    p[tid] = v;
}

// ---------------------------------------------------------------------------
extern "C" void kernel_launch(void* const* d_in, const int* in_sizes, int n_in,
                              void* d_out, int out_size)
{
    (void)in_sizes; (void)n_in; (void)out_size;
    const float* F_t = (const float*)d_in[0];
    const float* F_s = (const float*)d_in[1];
    const float* Wq  = (const float*)d_in[2];
    const float* bq  = (const float*)d_in[3];
    const float* Wk  = (const float*)d_in[4];
    const float* bk  = (const float*)d_in[5];
    const float* Wv  = (const float*)d_in[6];
    const float* bv  = (const float*)d_in[7];
    const float* Wp  = (const float*)d_in[8];
    const float* bp  = (const float*)d_in[9];
    float* out = (float*)d_out;

    float *tq, *tk, *tv, *q, *k, *v, *simb, *alpha, *beta, *ctx;
    __nv_bfloat16* A16;
    cudaGetSymbolAddress((void**)&tq, g_tq);
    cudaGetSymbolAddress((void**)&tk, g_tk);
    cudaGetSymbolAddress((void**)&tv, g_tv);
    cudaGetSymbolAddress((void**)&q, g_q);
    cudaGetSymbolAddress((void**)&k, g_k);
    cudaGetSymbolAddress((void**)&v, g_v);
    cudaGetSymbolAddress((void**)&simb, g_sim);
    cudaGetSymbolAddress((void**)&A16, g_A16);
    cudaGetSymbolAddress((void**)&alpha, g_alpha);
    cudaGetSymbolAddress((void**)&beta, g_beta);
    cudaGetSymbolAddress((void**)&ctx, g_ctx);

    // 1) QKV projections (conv1d k=1 == pointwise linear), 128x128 FFMA2 GEMM
    gemm128_kernel<<<dim3(DIM / 128, B * N1 / 128), 256>>>(F_t, Wq, bq, tq, B * N1, DIM, DIM);
    gemm128_kernel<<<dim3(DIM / 128, B * N2 / 128), 256>>>(F_s, Wk, bk, tk, B * N2, DIM, DIM);
    gemm128_kernel<<<dim3(DIM / 128, B * N2 / 128), 256>>>(F_s, Wv, bv, tv, B * N2, DIM, DIM);

    // 2) transpose to [B,H,Nx,64] (+ l2norm for q,k)
    {
        int warps_q = B * N1 * H;
        int warps_k = B * N2 * H;
        qk_transnorm_kernel<<<(warps_q * 32 + 255) / 256, 256>>>(tq, q, N1, 1);
        qk_transnorm_kernel<<<(warps_k * 32 + 255) / 256, 256>>>(tk, k, N2, 1);
        qk_transnorm_kernel<<<(warps_k * 32 + 255) / 256, 256>>>(tv, v, N2, 0);
    }

    // 3) sim (fp32) + bf16 Gibbs kernel A = exp((sim-1)/eps)
    sim_kernel<<<dim3(N2 / 64, N1 / 64, BH), 256>>>(q, k, simb, A16);

    // 4) Sinkhorn iterations (bf16 A, early exit), one CTA per (b,h)
    sinkhorn_kernel<<<BH, 512>>>(A16, alpha, beta);

    // 5) score @ v -> ctx [B*N1, 512]  (fp32 A recomputed from sim)
    av_kernel<<<dim3(N1 / 64, BH), 256>>>(simb, v, alpha, beta, ctx);

    // 6) projection + 7) row normalize (in place in d_out)
    gemm128_kernel<<<dim3(DIM / 128, B * N1 / 128), 256>>>(ctx, Wp, bp, out, B * N1, DIM, DIM);
    norm_rows_kernel<<<B * N1, 128>>>(out);
}